// round 1
// baseline (speedup 1.0000x reference)
#include <cuda_runtime.h>
#include <cuda_bf16.h>

#define SIDE 9
#define STATE 81
#define NA 5
#define H 32

// One thread per batch row. Scatter-add inverted into compile-time gather per
// destination cell; nsc value consumed immediately (store + reward + W1 FMA)
// so it never lives as a full 81-register array.
__global__ __launch_bounds__(256) void vpn_fused_kernel(
    const float* __restrict__ obs,          // (B, 3*STATE)
    const float* __restrict__ action_count, // (B, STATE, NA)
    const float* __restrict__ W1,           // (STATE, 32)
    const float* __restrict__ W2,           // (32, 32)
    const float* __restrict__ W3,           // (32, 1)
    const float* __restrict__ b3,           // (1,)
    float* __restrict__ out,                // [sym(B), imm(B), ret(B), nsc(B*81)]
    int B)
{
    __shared__ float sW1[STATE * H];
    __shared__ float sW2[H * H];
    __shared__ float sW3[H];
    __shared__ float sb3;

    for (int i = threadIdx.x; i < STATE * H; i += blockDim.x) sW1[i] = W1[i];
    for (int i = threadIdx.x; i < H * H; i += blockDim.x)     sW2[i] = W2[i];
    if (threadIdx.x < H)  sW3[threadIdx.x] = W3[threadIdx.x];
    if (threadIdx.x == 0) sb3 = b3[0];
    __syncthreads();

    const int b = blockIdx.x * blockDim.x + threadIdx.x;
    if (b >= B) return;

    const float* __restrict__ acr = action_count + (long long)b * (STATE * NA);
    const float* __restrict__ dem = obs + (long long)b * (3 * STATE) + 2 * STATE;
    float* __restrict__ nsc_out = out + (long long)3 * B + (long long)b * STATE;

    float h1[H];
    #pragma unroll
    for (int j = 0; j < H; j++) h1[j] = 0.0f;
    float imm = 0.0f;

    // For each destination cell d, gather all (s,a) pairs with dest(s,a)==d.
    // r,c are compile-time per unrolled iteration -> all branches resolve
    // statically, each action_count element is read exactly once.
    #pragma unroll
    for (int d = 0; d < STATE; d++) {
        const int r = d / SIDE;
        const int c = d % SIDE;

        float v = __ldg(&acr[d * NA + 0]);                       // a=0 stay
        if (r == 0)        v += __ldg(&acr[d * NA + 1]);          // up off-grid: stays
        if (r < SIDE - 1)  v += __ldg(&acr[(d + SIDE) * NA + 1]); // from below moving up
        if (r == SIDE - 1) v += __ldg(&acr[d * NA + 2]);          // down off-grid: stays
        if (r > 0)         v += __ldg(&acr[(d - SIDE) * NA + 2]); // from above moving down
        if (c == 0)        v += __ldg(&acr[d * NA + 3]);          // left off-grid: stays
        if (c < SIDE - 1)  v += __ldg(&acr[(d + 1) * NA + 3]);    // from right moving left
        if (c == SIDE - 1) v += __ldg(&acr[d * NA + 4]);          // right off-grid: stays
        if (c > 0)         v += __ldg(&acr[(d - 1) * NA + 4]);    // from left moving right

        nsc_out[d] = v;
        imm += fminf(v, __ldg(&dem[d]));

        const float4* __restrict__ w1row =
            reinterpret_cast<const float4*>(&sW1[d * H]);
        #pragma unroll
        for (int j4 = 0; j4 < H / 4; j4++) {
            float4 w = w1row[j4];
            h1[j4 * 4 + 0] = fmaf(v, w.x, h1[j4 * 4 + 0]);
            h1[j4 * 4 + 1] = fmaf(v, w.y, h1[j4 * 4 + 1]);
            h1[j4 * 4 + 2] = fmaf(v, w.z, h1[j4 * 4 + 2]);
            h1[j4 * 4 + 3] = fmaf(v, w.w, h1[j4 * 4 + 3]);
        }
    }

    // ReLU layer 1
    #pragma unroll
    for (int j = 0; j < H; j++) h1[j] = fmaxf(h1[j], 0.0f);

    // Layer 2: h2[j] = sum_i h1[i] * W2[i][j]
    float h2[H];
    #pragma unroll
    for (int j = 0; j < H; j++) h2[j] = 0.0f;
    #pragma unroll
    for (int i = 0; i < H; i++) {
        const float vi = h1[i];
        const float4* __restrict__ w2row =
            reinterpret_cast<const float4*>(&sW2[i * H]);
        #pragma unroll
        for (int j4 = 0; j4 < H / 4; j4++) {
            float4 w = w2row[j4];
            h2[j4 * 4 + 0] = fmaf(vi, w.x, h2[j4 * 4 + 0]);
            h2[j4 * 4 + 1] = fmaf(vi, w.y, h2[j4 * 4 + 1]);
            h2[j4 * 4 + 2] = fmaf(vi, w.z, h2[j4 * 4 + 2]);
            h2[j4 * 4 + 3] = fmaf(vi, w.w, h2[j4 * 4 + 3]);
        }
    }

    // Layer 3: scalar head
    float ret = sb3;
    #pragma unroll
    for (int j = 0; j < H; j++) ret = fmaf(fmaxf(h2[j], 0.0f), sW3[j], ret);

    out[b]                    = imm + ret; // symbolic_val
    out[(long long)B + b]     = imm;       // immediate_reward
    out[(long long)2 * B + b] = ret;       // next_return
}

extern "C" void kernel_launch(void* const* d_in, const int* in_sizes, int n_in,
                              void* d_out, int out_size) {
    const float* obs = (const float*)d_in[0];
    const float* action_count = (const float*)d_in[1];
    const float* W1 = (const float*)d_in[2];
    const float* W2 = (const float*)d_in[3];
    const float* W3 = (const float*)d_in[4];
    const float* b3 = (const float*)d_in[5];
    float* out = (float*)d_out;

    const int B = in_sizes[0] / (3 * STATE);
    const int threads = 256;
    const int blocks = (B + threads - 1) / threads;
    vpn_fused_kernel<<<blocks, threads>>>(obs, action_count, W1, W2, W3, b3, out, B);
}

// round 2
// speedup vs baseline: 1.8047x; 1.8047x over previous
#include <cuda_runtime.h>
#include <cuda_bf16.h>

#define SIDE 9
#define STATE 81
#define NA 5
#define H 32
#define WARPS_K1 8

// ---------------------------------------------------------------------------
// K1: warp-per-row. Coalesced stage of action_count row into smem, lanes
// compute nsc cells (l, l+32, l+64) with conflict-free LDS, coalesced STG of
// nsc, warp-reduced immediate reward.
// ---------------------------------------------------------------------------
__global__ __launch_bounds__(32 * WARPS_K1) void k1_nsc_reward(
    const float* __restrict__ obs,          // (B, 3*STATE)
    const float* __restrict__ acr_g,        // (B, STATE*NA)
    float* __restrict__ out,                // [sym(B), imm(B), ret(B), nsc(B*81)]
    int B)
{
    __shared__ float s[WARPS_K1][416];

    const int wid  = threadIdx.x >> 5;
    const int lane = threadIdx.x & 31;
    const long long row = (long long)blockIdx.x * WARPS_K1 + wid;
    if (row >= B) return;

    // Stage this row's action_count (coalesced: 128B per warp-LDG)
    const float* __restrict__ acr = acr_g + row * (STATE * NA);
    float* __restrict__ sp = s[wid];
    #pragma unroll
    for (int k = 0; k < 13; k++) {
        const int i = lane + 32 * k;
        if (i < STATE * NA) sp[i] = __ldg(&acr[i]);
    }
    __syncwarp();

    const float* __restrict__ dem = obs + row * (3 * STATE) + 2 * STATE;
    float* __restrict__ nout = out + 3LL * B + row * STATE;

    float imm = 0.0f;
    #pragma unroll
    for (int k = 0; k < 3; k++) {
        const int c = lane + 32 * k;
        if (c < STATE) {
            const int r   = c / SIDE;
            const int col = c - r * SIDE;
            // gather all (s,a) with dest == c; banks = (5c+k)%32, conflict-free
            float v = sp[c * NA + 0];
            if (r == 0)        v += sp[c * NA + 1];
            if (r < SIDE - 1)  v += sp[(c + SIDE) * NA + 1];
            if (r == SIDE - 1) v += sp[c * NA + 2];
            if (r > 0)         v += sp[(c - SIDE) * NA + 2];
            if (col == 0)      v += sp[c * NA + 3];
            if (col < SIDE - 1)v += sp[(c + 1) * NA + 3];
            if (col == SIDE-1) v += sp[c * NA + 4];
            if (col > 0)       v += sp[(c - 1) * NA + 4];

            nout[c] = v;                       // coalesced STG
            imm += fminf(v, __ldg(&dem[c]));   // coalesced LDG
        }
    }

    #pragma unroll
    for (int o = 16; o; o >>= 1) imm += __shfl_xor_sync(0xffffffffu, imm, o);
    if (lane == 0) out[(long long)B + row] = imm;
}

// ---------------------------------------------------------------------------
// Packed f32x2 helpers (sm_103a FFMA2)
// ---------------------------------------------------------------------------
__device__ __forceinline__ unsigned long long pack2(float x) {
    unsigned long long r;
    asm("mov.b64 %0, {%1, %1};" : "=l"(r) : "f"(x));
    return r;
}
__device__ __forceinline__ void ffma2(unsigned long long& d,
                                      unsigned long long a,
                                      unsigned long long b) {
    asm("fma.rn.f32x2 %0, %1, %2, %0;" : "+l"(d) : "l"(a), "l"(b));
}
__device__ __forceinline__ void unpack2(unsigned long long p, float& lo, float& hi) {
    asm("mov.b64 {%0, %1}, %2;" : "=f"(lo), "=f"(hi) : "l"(p));
}

// ---------------------------------------------------------------------------
// K2: thread-per-row MLP. nsc re-read from out (L2-hot, 324B/row -> small L1
// working set). Weights in smem, pair-packed FFMA2 halves the FMA count.
// ---------------------------------------------------------------------------
__global__ __launch_bounds__(256) void k2_mlp(
    const float* __restrict__ W1,
    const float* __restrict__ W2,
    const float* __restrict__ W3,
    const float* __restrict__ b3,
    float* __restrict__ out,
    int B)
{
    __shared__ float sW1[STATE * H];
    __shared__ float sW2[H * H];
    __shared__ float sW3[H];
    __shared__ float sb3;

    for (int i = threadIdx.x; i < STATE * H; i += blockDim.x) sW1[i] = W1[i];
    for (int i = threadIdx.x; i < H * H; i += blockDim.x)     sW2[i] = W2[i];
    if (threadIdx.x < H)  sW3[threadIdx.x] = W3[threadIdx.x];
    if (threadIdx.x == 0) sb3 = b3[0];
    __syncthreads();

    const long long b = (long long)blockIdx.x * blockDim.x + threadIdx.x;
    if (b >= B) return;

    const float* __restrict__ nsc = out + 3LL * B + b * STATE;

    unsigned long long h1p[H / 2];
    #pragma unroll
    for (int j = 0; j < H / 2; j++) h1p[j] = 0ULL;

    // Layer 1: h1 += nsc[d] * W1[d][:]   (broadcast smem reads of W1 row)
    #pragma unroll 3
    for (int d = 0; d < STATE; d++) {
        const unsigned long long vd = pack2(__ldg(&nsc[d]));
        const ulonglong2* __restrict__ w1p =
            reinterpret_cast<const ulonglong2*>(&sW1[d * H]);
        #pragma unroll
        for (int q = 0; q < H / 4; q++) {
            ulonglong2 w = w1p[q];
            ffma2(h1p[q * 2 + 0], vd, w.x);
            ffma2(h1p[q * 2 + 1], vd, w.y);
        }
    }

    // ReLU + unpack
    float h1[H];
    #pragma unroll
    for (int j = 0; j < H / 2; j++) {
        float lo, hi;
        unpack2(h1p[j], lo, hi);
        h1[2 * j + 0] = fmaxf(lo, 0.0f);
        h1[2 * j + 1] = fmaxf(hi, 0.0f);
    }

    // Layer 2
    unsigned long long h2p[H / 2];
    #pragma unroll
    for (int j = 0; j < H / 2; j++) h2p[j] = 0ULL;
    #pragma unroll
    for (int i = 0; i < H; i++) {
        const unsigned long long vi = pack2(h1[i]);
        const ulonglong2* __restrict__ w2p =
            reinterpret_cast<const ulonglong2*>(&sW2[i * H]);
        #pragma unroll
        for (int q = 0; q < H / 4; q++) {
            ulonglong2 w = w2p[q];
            ffma2(h2p[q * 2 + 0], vi, w.x);
            ffma2(h2p[q * 2 + 1], vi, w.y);
        }
    }

    // Layer 3: scalar head
    float ret = sb3;
    #pragma unroll
    for (int j = 0; j < H / 2; j++) {
        float lo, hi;
        unpack2(h2p[j], lo, hi);
        ret = fmaf(fmaxf(lo, 0.0f), sW3[2 * j + 0], ret);
        ret = fmaf(fmaxf(hi, 0.0f), sW3[2 * j + 1], ret);
    }

    const float imm = out[(long long)B + b];
    out[b]                    = imm + ret;  // symbolic_val
    out[2LL * (long long)B + b] = ret;      // next_return
}

extern "C" void kernel_launch(void* const* d_in, const int* in_sizes, int n_in,
                              void* d_out, int out_size) {
    const float* obs = (const float*)d_in[0];
    const float* action_count = (const float*)d_in[1];
    const float* W1 = (const float*)d_in[2];
    const float* W2 = (const float*)d_in[3];
    const float* W3 = (const float*)d_in[4];
    const float* b3 = (const float*)d_in[5];
    float* out = (float*)d_out;

    const int B = in_sizes[0] / (3 * STATE);

    const int blocks1 = (B + WARPS_K1 - 1) / WARPS_K1;
    k1_nsc_reward<<<blocks1, 32 * WARPS_K1>>>(obs, action_count, out, B);

    const int threads2 = 256;
    const int blocks2 = (B + threads2 - 1) / threads2;
    k2_mlp<<<blocks2, threads2>>>(W1, W2, W3, b3, out, B);
}

// round 3
// speedup vs baseline: 1.8760x; 1.0395x over previous
#include <cuda_runtime.h>
#include <cuda_bf16.h>

#define SIDE 9
#define STATE 81
#define NA 5
#define H 32
#define WARPS_K1 8
#define K2_THREADS 256
#define K2_ROWS 256   // rows per block == threads per block

// ---------------------------------------------------------------------------
// K1: warp-per-row scatter + reward (near DRAM-bound, kept from round 2).
// ---------------------------------------------------------------------------
__global__ __launch_bounds__(32 * WARPS_K1) void k1_nsc_reward(
    const float* __restrict__ obs,          // (B, 3*STATE)
    const float* __restrict__ acr_g,        // (B, STATE*NA)
    float* __restrict__ out,                // [sym(B), imm(B), ret(B), nsc(B*81)]
    int B)
{
    __shared__ float s[WARPS_K1][416];

    const int wid  = threadIdx.x >> 5;
    const int lane = threadIdx.x & 31;
    const long long row = (long long)blockIdx.x * WARPS_K1 + wid;
    if (row >= B) return;

    const float* __restrict__ acr = acr_g + row * (STATE * NA);
    float* __restrict__ sp = s[wid];
    #pragma unroll
    for (int k = 0; k < 13; k++) {
        const int i = lane + 32 * k;
        if (i < STATE * NA) sp[i] = __ldg(&acr[i]);
    }
    __syncwarp();

    const float* __restrict__ dem = obs + row * (3 * STATE) + 2 * STATE;
    float* __restrict__ nout = out + 3LL * B + row * STATE;

    float imm = 0.0f;
    #pragma unroll
    for (int k = 0; k < 3; k++) {
        const int c = lane + 32 * k;
        if (c < STATE) {
            const int r   = c / SIDE;
            const int col = c - r * SIDE;
            float v = sp[c * NA + 0];
            if (r == 0)        v += sp[c * NA + 1];
            if (r < SIDE - 1)  v += sp[(c + SIDE) * NA + 1];
            if (r == SIDE - 1) v += sp[c * NA + 2];
            if (r > 0)         v += sp[(c - SIDE) * NA + 2];
            if (col == 0)      v += sp[c * NA + 3];
            if (col < SIDE - 1)v += sp[(c + 1) * NA + 3];
            if (col == SIDE-1) v += sp[c * NA + 4];
            if (col > 0)       v += sp[(c - 1) * NA + 4];

            nout[c] = v;
            imm += fminf(v, __ldg(&dem[c]));
        }
    }

    #pragma unroll
    for (int o = 16; o; o >>= 1) imm += __shfl_xor_sync(0xffffffffu, imm, o);
    if (lane == 0) out[(long long)B + row] = imm;
}

// ---------------------------------------------------------------------------
// Packed f32x2 helpers (sm_103a FFMA2)
// ---------------------------------------------------------------------------
__device__ __forceinline__ unsigned long long pack2(float x) {
    unsigned long long r;
    asm("mov.b64 %0, {%1, %1};" : "=l"(r) : "f"(x));
    return r;
}
__device__ __forceinline__ void ffma2(unsigned long long& d,
                                      unsigned long long a,
                                      unsigned long long b) {
    asm("fma.rn.f32x2 %0, %1, %2, %0;" : "+l"(d) : "l"(a), "l"(b));
}
__device__ __forceinline__ void unpack2(unsigned long long p, float& lo, float& hi) {
    asm("mov.b64 {%0, %1}, %2;" : "=f"(lo), "=f"(hi) : "l"(p));
}

// ---------------------------------------------------------------------------
// K2: thread-per-row MLP with coalesced smem transpose of nsc.
// Dynamic smem layout: [nsc 256*81 | W1 81*32 | W2 32*32 | W3 32 | b3 1]
// ---------------------------------------------------------------------------
__global__ __launch_bounds__(K2_THREADS) void k2_mlp(
    const float* __restrict__ W1,
    const float* __restrict__ W2,
    const float* __restrict__ W3,
    const float* __restrict__ b3,
    float* __restrict__ out,
    int B)
{
    extern __shared__ float smem[];
    float* s_nsc = smem;                          // K2_ROWS * STATE
    float* sW1   = s_nsc + K2_ROWS * STATE;       // STATE * H
    float* sW2   = sW1 + STATE * H;               // H * H
    float* sW3   = sW2 + H * H;                   // H
    float* sb3   = sW3 + H;                       // 1

    for (int i = threadIdx.x; i < STATE * H; i += blockDim.x) sW1[i] = W1[i];
    for (int i = threadIdx.x; i < H * H; i += blockDim.x)     sW2[i] = W2[i];
    if (threadIdx.x < H)  sW3[threadIdx.x] = W3[threadIdx.x];
    if (threadIdx.x == 0) sb3[0] = b3[0];

    const int wid  = threadIdx.x >> 5;
    const int lane = threadIdx.x & 31;
    const long long blockRow0 = (long long)blockIdx.x * K2_ROWS;
    const long long warpRow0  = blockRow0 + wid * 32;

    // Coalesced stage: this warp's 32 rows of nsc are 2592 contiguous floats.
    const float* __restrict__ nsc_g = out + 3LL * B;
    if (warpRow0 + 32 <= B) {
        const float* __restrict__ src = nsc_g + warpRow0 * STATE;
        float* __restrict__ dst = s_nsc + wid * (32 * STATE);
        #pragma unroll
        for (int k = 0; k < STATE; k++)
            dst[k * 32 + lane] = __ldg(&src[k * 32 + lane]);
    } else {
        // tail: guarded scalar path
        for (int r = 0; r < 32; r++) {
            const long long row = warpRow0 + r;
            if (row < B)
                for (int d = lane; d < STATE; d += 32)
                    s_nsc[(wid * 32 + r) * STATE + d] = nsc_g[row * STATE + d];
        }
    }
    __syncthreads();   // weights + nsc visible

    const long long b = blockRow0 + threadIdx.x;
    if (b >= B) return;

    // Bank-conflict-free: address t*81+d -> bank (17t+d)%32, a lane permutation.
    const float* __restrict__ myn = s_nsc + threadIdx.x * STATE;

    unsigned long long h1p[H / 2];
    #pragma unroll
    for (int j = 0; j < H / 2; j++) h1p[j] = 0ULL;

    #pragma unroll 3
    for (int d = 0; d < STATE; d++) {
        const unsigned long long vd = pack2(myn[d]);
        const ulonglong2* __restrict__ w1p =
            reinterpret_cast<const ulonglong2*>(&sW1[d * H]);
        #pragma unroll
        for (int q = 0; q < H / 4; q++) {
            ulonglong2 w = w1p[q];
            ffma2(h1p[q * 2 + 0], vd, w.x);
            ffma2(h1p[q * 2 + 1], vd, w.y);
        }
    }

    float h1[H];
    #pragma unroll
    for (int j = 0; j < H / 2; j++) {
        float lo, hi;
        unpack2(h1p[j], lo, hi);
        h1[2 * j + 0] = fmaxf(lo, 0.0f);
        h1[2 * j + 1] = fmaxf(hi, 0.0f);
    }

    unsigned long long h2p[H / 2];
    #pragma unroll
    for (int j = 0; j < H / 2; j++) h2p[j] = 0ULL;
    #pragma unroll
    for (int i = 0; i < H; i++) {
        const unsigned long long vi = pack2(h1[i]);
        const ulonglong2* __restrict__ w2p =
            reinterpret_cast<const ulonglong2*>(&sW2[i * H]);
        #pragma unroll
        for (int q = 0; q < H / 4; q++) {
            ulonglong2 w = w2p[q];
            ffma2(h2p[q * 2 + 0], vi, w.x);
            ffma2(h2p[q * 2 + 1], vi, w.y);
        }
    }

    float ret = sb3[0];
    #pragma unroll
    for (int j = 0; j < H / 2; j++) {
        float lo, hi;
        unpack2(h2p[j], lo, hi);
        ret = fmaf(fmaxf(lo, 0.0f), sW3[2 * j + 0], ret);
        ret = fmaf(fmaxf(hi, 0.0f), sW3[2 * j + 1], ret);
    }

    const float imm = out[(long long)B + b];
    out[b]                      = imm + ret;  // symbolic_val
    out[2LL * (long long)B + b] = ret;        // next_return
}

static const int K2_SMEM_BYTES =
    (K2_ROWS * STATE + STATE * H + H * H + H + 1) * (int)sizeof(float);

extern "C" void kernel_launch(void* const* d_in, const int* in_sizes, int n_in,
                              void* d_out, int out_size) {
    const float* obs = (const float*)d_in[0];
    const float* action_count = (const float*)d_in[1];
    const float* W1 = (const float*)d_in[2];
    const float* W2 = (const float*)d_in[3];
    const float* W3 = (const float*)d_in[4];
    const float* b3 = (const float*)d_in[5];
    float* out = (float*)d_out;

    const int B = in_sizes[0] / (3 * STATE);

    cudaFuncSetAttribute(k2_mlp, cudaFuncAttributeMaxDynamicSharedMemorySize,
                         K2_SMEM_BYTES);

    const int blocks1 = (B + WARPS_K1 - 1) / WARPS_K1;
    k1_nsc_reward<<<blocks1, 32 * WARPS_K1>>>(obs, action_count, out, B);

    const int blocks2 = (B + K2_ROWS - 1) / K2_ROWS;
    k2_mlp<<<blocks2, K2_THREADS, K2_SMEM_BYTES>>>(W1, W2, W3, b3, out, B);
}